// round 15
// baseline (speedup 1.0000x reference)
#include <cuda_runtime.h>
#include <cuda_bf16.h>
#include <cuda_fp16.h>
#include <cstdint>

// Problem constants
#define T_TOK 8192
#define K_CODE 8192
#define C_DIM 512
#define KSPLIT 512             // plain bf16 GEMM

// EMA / loss constants
#define DECAY_F 0.99f
#define OMD_F ((float)(1.0 - 0.99))
#define EPS_F 1e-5f
#define KEPS_F 0.08192f

#define MARGIN 0.125f          // ~89 sigma of bf16 dist error + fp16 quantization
#define CAPG (1 << 22)         // global candidate list capacity (4M)

// -------- scratch (device globals; no allocation allowed) --------
__device__ __align__(16) unsigned long long g_keys[T_TOK];
__device__ __align__(16) unsigned g_amin[T_TOK];                        // f2ord(shifted min)
__device__ __align__(16) float g_stok[T_TOK];
__device__ __align__(16) float g_hcode[K_CODE];
__device__ __align__(16) float g_counts[K_CODE];
__device__ __align__(16) float g_embed_sum[(size_t)K_CODE * C_DIM];
__device__ __align__(16) __nv_bfloat16 g_A2h[(size_t)T_TOK * KSPLIT];   // bf16(Z)
__device__ __align__(16) __nv_bfloat16 g_B2h[(size_t)K_CODE * KSPLIT];  // bf16(E)
__device__ __align__(16) __half g_dh[(size_t)T_TOK * K_CODE];           // fp16 shifted dists
__device__ __align__(16) unsigned g_cand[CAPG];                         // (t<<13)|j
__device__ int g_ncand;
__device__ double g_loss;
__device__ float g_nsum;

// ------------------------------------------------------------------
// helpers
// ------------------------------------------------------------------
__device__ __forceinline__ uint32_t smem_u32(const void* p) {
    uint32_t a;
    asm("{ .reg .u64 t; cvta.to.shared.u64 t, %1; cvt.u32.u64 %0, t; }"
        : "=r"(a) : "l"(p));
    return a;
}
__device__ __forceinline__ unsigned f2ord(float f) {
    unsigned u = __float_as_uint(f);
    return (u & 0x80000000u) ? ~u : (u | 0x80000000u);
}
__device__ __forceinline__ float ord2f(unsigned u) {
    return (u & 0x80000000u) ? __uint_as_float(u & 0x7FFFFFFFu)
                             : __uint_as_float(~u);
}

#define LDSM_X4(r0, r1, r2, r3, addr) \
    asm volatile("ldmatrix.sync.aligned.m8n8.x4.shared.b16 {%0,%1,%2,%3}, [%4];" \
                 : "=r"(r0), "=r"(r1), "=r"(r2), "=r"(r3) : "r"(addr))

// ------------------------------------------------------------------
// K0: init scratch
// ------------------------------------------------------------------
__global__ void k_init() {
    size_t i = (size_t)blockIdx.x * blockDim.x + threadIdx.x;
    size_t stride = (size_t)gridDim.x * blockDim.x;
    float4 z4 = make_float4(0.f, 0.f, 0.f, 0.f);
    float4* es4 = (float4*)g_embed_sum;
    const size_t n4 = (size_t)K_CODE * C_DIM / 4;
    for (size_t j = i; j < n4; j += stride) es4[j] = z4;
    for (size_t j = i; j < K_CODE; j += stride) g_counts[j] = 0.f;
    for (size_t j = i; j < T_TOK; j += stride) { g_keys[j] = ~0ull; g_amin[j] = 0xFFFFFFFFu; }
    if (i == 0) { g_loss = 0.0; g_nsum = 0.f; g_ncand = 0; }
}

// ------------------------------------------------------------------
// K1: fused row norms + bf16 convert (one warp per row; rows 0..T-1 = Z,
//     rows T..T+K-1 = E). Norm computed EXACTLY like the R5 kernel.
// ------------------------------------------------------------------
__global__ void k_prep(const float* __restrict__ Z, const float* __restrict__ E) {
    int warp = (int)((blockIdx.x * blockDim.x + threadIdx.x) >> 5);
    int lane = threadIdx.x & 31;
    if (warp >= T_TOK + K_CODE) return;
    const bool isZ = warp < T_TOK;
    const int row = isZ ? warp : warp - T_TOK;
    const float* p = isZ ? (Z + (size_t)row * C_DIM) : (E + (size_t)row * C_DIM);
    __nv_bfloat16* q = isZ ? (g_A2h + (size_t)row * KSPLIT) : (g_B2h + (size_t)row * KSPLIT);
    const float4* p4 = (const float4*)p;
    float s = 0.f;
#pragma unroll
    for (int i = 0; i < C_DIM / 128; i++) {
        float4 v = p4[lane + i * 32];
        s += v.x * v.x + v.y * v.y + v.z * v.z + v.w * v.w;
        __nv_bfloat162* q2 = (__nv_bfloat162*)(q + (lane + i * 32) * 4);
        q2[0] = __nv_bfloat162(__float2bfloat16(v.x), __float2bfloat16(v.y));
        q2[1] = __nv_bfloat162(__float2bfloat16(v.z), __float2bfloat16(v.w));
    }
#pragma unroll
    for (int off = 16; off; off >>= 1) s += __shfl_xor_sync(0xFFFFFFFFu, s, off);
    if (lane == 0) {
        if (isZ) g_stok[row] = s;
        else     g_hcode[row] = s;
    }
}

// ------------------------------------------------------------------
// K2: bf16 mma.sync GEMM -> fp16 SHIFTED dists (h - 2*dot) + f2ord minima.
//   CTA 128x128, 128 threads, 4 warps (2x2), warp tile 64x64. 2 CTAs/SM.
// ------------------------------------------------------------------
#define TILE_M 128
#define TILE_N 128
#define BKB 32
#define RST 40
#define STAGE_BF ((TILE_M + TILE_N) * RST)      // 10240 bf16
#define STAGE_BYTES (STAGE_BF * 2)              // 20480
#define NSTAGE 4
#define SMEMB (NSTAGE * STAGE_BYTES)            // 81920
#define NIT (KSPLIT / BKB)                      // 16

__global__ __launch_bounds__(128, 2) void k_gemm_bf16() {
    extern __shared__ __align__(16) __nv_bfloat16 smb[];
    const uint32_t sm_base = smem_u32(smb);
    const int tid = threadIdx.x;
    const int wid = tid >> 5, lane = tid & 31;
    const int g = lane >> 2, t = lane & 3;
    const int wm = wid >> 1, wn = wid & 1;     // 2 x 2 warp grid
    const int bm = blockIdx.y * TILE_M;
    const int bn = blockIdx.x * TILE_N;

    float acc[4][8][4];
#pragma unroll
    for (int a = 0; a < 4; a++)
#pragma unroll
        for (int b = 0; b < 8; b++)
#pragma unroll
            for (int c = 0; c < 4; c++) acc[a][b][c] = 0.f;

    // cp.async mapping: 1024 16B-chunks per stage (256 rows x 4 segs), 8/thread
    const __nv_bfloat16* srcp[8];
    uint32_t dsto[8];
#pragma unroll
    for (int i = 0; i < 8; i++) {
        int q = tid + i * 128;
        int row = q >> 2;
        int seg = q & 3;                 // 8 bf16 per 16B segment
        srcp[i] = (row < TILE_M)
                    ? (g_A2h + (size_t)(bm + row) * KSPLIT + seg * 8)
                    : (g_B2h + (size_t)(bn + (row - TILE_M)) * KSPLIT + seg * 8);
        dsto[i] = (uint32_t)(row * RST + seg * 8) * 2u;
    }

    auto load_stage = [&](int c) {
        uint32_t buf = (uint32_t)(c % NSTAGE) * STAGE_BYTES;
#pragma unroll
        for (int i = 0; i < 8; i++) {
            asm volatile("cp.async.cg.shared.global [%0], [%1], 16;"
                         :: "r"(sm_base + buf + dsto[i]),
                            "l"(srcp[i] + (size_t)c * BKB) : "memory");
        }
        asm volatile("cp.async.commit_group;" ::: "memory");
    };

    // ldmatrix per-lane element offsets (bf16 elements within a stage)
    const int lrow = lane & 7, blk = lane >> 3;
    const uint32_t a_elem = (uint32_t)((wm * 64 + (blk & 1) * 8 + lrow) * RST + (blk >> 1) * 8);
    uint32_t b_elem[4];
#pragma unroll
    for (int nfp = 0; nfp < 4; nfp++)
        b_elem[nfp] = (uint32_t)((TILE_M + wn * 64 + nfp * 16 + (blk >> 1) * 8 + lrow) * RST
                                 + (blk & 1) * 8);

    load_stage(0);
    load_stage(1);
    load_stage(2);

    for (int c = 0; c < NIT; c++) {
        if (c + 2 < NIT)      asm volatile("cp.async.wait_group 2;" ::: "memory");
        else if (c + 1 < NIT) asm volatile("cp.async.wait_group 1;" ::: "memory");
        else                  asm volatile("cp.async.wait_group 0;" ::: "memory");
        __syncthreads();                 // all warps past compute of stage c-1
        if (c + 3 < NIT) load_stage(c + 3);

        const uint32_t sbuf = sm_base + (uint32_t)(c % NSTAGE) * STAGE_BYTES;

#pragma unroll
        for (int ks = 0; ks < 2; ks++) {
            const uint32_t k0 = ks * 16;
            uint32_t af[4][4];
#pragma unroll
            for (int mf = 0; mf < 4; mf++) {
                uint32_t addr = sbuf + (a_elem + (uint32_t)(mf * 16 * RST) + k0) * 2u;
                LDSM_X4(af[mf][0], af[mf][1], af[mf][2], af[mf][3], addr);
            }
            uint32_t bfr[8][2];
#pragma unroll
            for (int nfp = 0; nfp < 4; nfp++) {
                uint32_t addr = sbuf + (b_elem[nfp] + k0) * 2u;
                LDSM_X4(bfr[2 * nfp][0], bfr[2 * nfp][1],
                        bfr[2 * nfp + 1][0], bfr[2 * nfp + 1][1], addr);
            }
#pragma unroll
            for (int mf = 0; mf < 4; mf++)
#pragma unroll
                for (int nf = 0; nf < 8; nf++) {
                    float* d = acc[mf][nf];
                    asm volatile(
                        "mma.sync.aligned.m16n8k16.row.col.f32.bf16.bf16.f32 "
                        "{%0,%1,%2,%3}, {%4,%5,%6,%7}, {%8,%9}, {%0,%1,%2,%3};"
                        : "+f"(d[0]), "+f"(d[1]), "+f"(d[2]), "+f"(d[3])
                        : "r"(af[mf][0]), "r"(af[mf][1]), "r"(af[mf][2]), "r"(af[mf][3]),
                          "r"(bfr[nf][0]), "r"(bfr[nf][1]));
                }
        }
    }

    // ---- epilogue: store fp16 SHIFTED dists (h - 2*dot) + f2ord row minima ----
#pragma unroll
    for (int mf = 0; mf < 4; mf++) {
        int r0 = bm + wm * 64 + mf * 16 + g;
        float m0 = 3.4e38f, m1 = 3.4e38f;
#pragma unroll
        for (int nf = 0; nf < 8; nf++) {
            int c0 = bn + wn * 64 + nf * 8 + 2 * t;
            float h0 = g_hcode[c0];
            float h1 = g_hcode[c0 + 1];
            const float* d = acc[mf][nf];
            float v00 = h0 - 2.0f * d[0], v01 = h1 - 2.0f * d[1];
            float v10 = h0 - 2.0f * d[2], v11 = h1 - 2.0f * d[3];
            *(__half2*)(g_dh + (size_t)r0 * K_CODE + c0) =
                __floats2half2_rn(v00, v01);
            *(__half2*)(g_dh + (size_t)(r0 + 8) * K_CODE + c0) =
                __floats2half2_rn(v10, v11);
            m0 = fminf(m0, fminf(v00, v01));
            m1 = fminf(m1, fminf(v10, v11));
        }
#pragma unroll
        for (int off = 1; off <= 2; off <<= 1) {
            m0 = fminf(m0, __shfl_xor_sync(0xFFFFFFFFu, m0, off));
            m1 = fminf(m1, __shfl_xor_sync(0xFFFFFFFFu, m1, off));
        }
        if (t == 0) {
            atomicMin(&g_amin[r0], f2ord(m0));
            atomicMin(&g_amin[r0 + 8], f2ord(m1));
        }
    }
}

// ------------------------------------------------------------------
// K2b: flat band scan. Grid-stride over the fp16 dist matrix, one uint4
//   (= 8 fp16, 16 bytes) per iteration; hits appended to a global list.
//   R13 bug fixed: chunk is 8 halves (uint4), 1024 chunks per row.
// ------------------------------------------------------------------
__global__ __launch_bounds__(256) void k_scan() {
    const size_t nchunk = (size_t)T_TOK * K_CODE / 8;
    size_t i = (size_t)blockIdx.x * blockDim.x + threadIdx.x;
    const size_t stride = (size_t)gridDim.x * blockDim.x;
    for (; i < nchunk; i += stride) {
        const int t = (int)(i >> 10);           // 1024 chunks per row (8192/8)
        const int col0 = (int)(i & 1023) << 3;
        const float thr = ord2f(g_amin[t]) + MARGIN;
        const uint4 v4 = *(const uint4*)(g_dh + (size_t)t * K_CODE + col0);
        const __half2* h2 = (const __half2*)&v4;   // 4 half2 = 8 values
#pragma unroll
        for (int q = 0; q < 4; q++) {
            float2 f = __half22float2(h2[q]);
            if (f.x < thr) {
                int p = atomicAdd(&g_ncand, 1);
                if (p < CAPG) g_cand[p] = ((unsigned)t << 13) | (unsigned)(col0 + 2 * q);
            }
            if (f.y < thr) {
                int p = atomicAdd(&g_ncand, 1);
                if (p < CAPG) g_cand[p] = ((unsigned)t << 13) | (unsigned)(col0 + 2 * q + 1);
            }
        }
    }
}

// ------------------------------------------------------------------
// K2c: exact re-check over the candidate list. ONE THREAD per candidate,
//   sequential ascending-k fmaf chain == the R5 oracle's operation order
//   -> g_keys bit-identical to the R5-passing kernel.
// ------------------------------------------------------------------
__global__ __launch_bounds__(256) void k_rlist(const float* __restrict__ Z,
                                               const float* __restrict__ E) {
    int n = g_ncand;
    if (n > CAPG) n = CAPG;
    int i = blockIdx.x * blockDim.x + threadIdx.x;
    const int stride = gridDim.x * blockDim.x;
    for (; i < n; i += stride) {
        const unsigned c = g_cand[i];
        const int t = (int)(c >> 13);
        const int j = (int)(c & 8191u);
        const float* zp = Z + (size_t)t * C_DIM;
        const float* ep = E + (size_t)j * C_DIM;
        float a = 0.f;
#pragma unroll 8
        for (int k = 0; k < C_DIM; k++) a = fmaf(zp[k], ep[k], a);  // sequential chain
        float dist = (g_stok[t] - 2.0f * a) + g_hcode[j];
        unsigned long long key = ((unsigned long long)f2ord(dist) << 32) | (unsigned)j;
        atomicMin(&g_keys[t], key);
    }
}

// ------------------------------------------------------------------
// K3: per-token: gather z_q, straight-through out, loss, counts,
//     embed_sum scatter. One block (128 threads) per token.
// ------------------------------------------------------------------
__global__ void k_token(const float* __restrict__ Z, const float* __restrict__ E,
                        float* __restrict__ out_zq, float* __restrict__ out_idx) {
    __shared__ float red[4];
    const int t = blockIdx.x;
    const int idx = (int)(g_keys[t] & 0xFFFFFFFFull);
    const float4* z4 = (const float4*)(Z + (size_t)t * C_DIM);
    const float4* e4 = (const float4*)(E + (size_t)idx * C_DIM);
    float4* o4 = (float4*)(out_zq + (size_t)t * C_DIM);
    float* es = g_embed_sum + (size_t)idx * C_DIM;

    const int i = threadIdx.x;
    float4 zv = z4[i];
    float4 ev = e4[i];
    float4 o;
    o.x = zv.x + (ev.x - zv.x);
    o.y = zv.y + (ev.y - zv.y);
    o.z = zv.z + (ev.z - zv.z);
    o.w = zv.w + (ev.w - zv.w);
    o4[i] = o;
    float dx = zv.x - ev.x, dy = zv.y - ev.y, dz = zv.z - ev.z, dw = zv.w - ev.w;
    float lsum = dx * dx + dy * dy + dz * dz + dw * dw;

    atomicAdd(&es[4 * i + 0], zv.x);
    atomicAdd(&es[4 * i + 1], zv.y);
    atomicAdd(&es[4 * i + 2], zv.z);
    atomicAdd(&es[4 * i + 3], zv.w);

#pragma unroll
    for (int off = 16; off; off >>= 1) lsum += __shfl_xor_sync(0xFFFFFFFFu, lsum, off);
    if ((i & 31) == 0) red[i >> 5] = lsum;
    __syncthreads();
    if (i == 0) {
        float tot = red[0] + red[1] + red[2] + red[3];
        out_idx[t] = (float)idx;
        atomicAdd(&g_counts[idx], 1.0f);
        atomicAdd(&g_loss, (double)tot);
    }
}

// ------------------------------------------------------------------
// K4: new_cluster_size + its global sum
// ------------------------------------------------------------------
__global__ void k_cluster(const float* __restrict__ cs, float* __restrict__ out_cs) {
    __shared__ float red[8];
    int k = blockIdx.x * 256 + threadIdx.x;
    float v = cs[k] * DECAY_F + g_counts[k] * OMD_F;
    out_cs[k] = v;
    float sum = v;
#pragma unroll
    for (int off = 16; off; off >>= 1) sum += __shfl_xor_sync(0xFFFFFFFFu, sum, off);
    if ((threadIdx.x & 31) == 0) red[threadIdx.x >> 5] = sum;
    __syncthreads();
    if (threadIdx.x == 0) {
        float tot = 0.f;
#pragma unroll
        for (int w = 0; w < 8; w++) tot += red[w];
        atomicAdd(&g_nsum, tot);
    }
}

// ------------------------------------------------------------------
// K5: new_embed_avg, new_codebook, vq_loss scalar.
// ------------------------------------------------------------------
__global__ void k_final(const float* __restrict__ ea, const float* __restrict__ ncs_arr,
                        float* __restrict__ out_cb, float* __restrict__ out_ea,
                        float* __restrict__ out_loss) {
    const int k = blockIdx.x;
    if (k == 0 && threadIdx.x == 0) {
        out_loss[0] = 0.25f * (float)(g_loss / (double)((size_t)T_TOK * C_DIM));
    }
    float n = fmaxf(g_nsum, 1.0f);
    float ncs = ncs_arr[k];
    float sm = (ncs + EPS_F) / (n + KEPS_F) * n;

    const float4* a4 = (const float4*)(ea + (size_t)k * C_DIM);
    const float4* s4 = (const float4*)(g_embed_sum + (size_t)k * C_DIM);
    const int i = threadIdx.x;
    float4 av = a4[i];
    float4 sv = s4[i];
    float ne[4];
    ne[0] = av.x * DECAY_F + sv.x * OMD_F;
    ne[1] = av.y * DECAY_F + sv.y * OMD_F;
    ne[2] = av.z * DECAY_F + sv.z * OMD_F;
    ne[3] = av.w * DECAY_F + sv.w * OMD_F;
    size_t base = (size_t)k * C_DIM + 4 * i;
#pragma unroll
    for (int j = 0; j < 4; j++) {
        out_ea[base + j] = ne[j];
        out_cb[base + j] = ne[j] / sm;   // out offsets are 1 mod 4 -> scalar stores
    }
}

// ------------------------------------------------------------------
// launch
// ------------------------------------------------------------------
extern "C" void kernel_launch(void* const* d_in, const int* in_sizes, int n_in,
                              void* d_out, int out_size) {
    const float* Z  = (const float*)d_in[0];
    const float* E  = (const float*)d_in[1];
    const float* CS = (const float*)d_in[2];
    const float* EA = (const float*)d_in[3];

    float* out = (float*)d_out;
    float* out_zq   = out;
    float* out_idx  = out_zq + (size_t)T_TOK * C_DIM;
    float* out_loss = out_idx + T_TOK;
    float* out_cb   = out_loss + 1;
    float* out_cs   = out_cb + (size_t)K_CODE * C_DIM;
    float* out_ea   = out_cs + K_CODE;

    cudaFuncSetAttribute(k_gemm_bf16, cudaFuncAttributeMaxDynamicSharedMemorySize, SMEMB);

    k_init<<<2048, 256>>>();
    k_prep<<<(T_TOK + K_CODE) / 8, 256>>>(Z, E);
    dim3 grid(K_CODE / TILE_N, T_TOK / TILE_M);   // (64, 64)
    k_gemm_bf16<<<grid, 128, SMEMB>>>();
    k_scan<<<2048, 256>>>();
    k_rlist<<<1024, 256>>>(Z, E);
    k_token<<<T_TOK, 128>>>(Z, E, out_zq, out_idx);
    k_cluster<<<K_CODE / 256, 256>>>(CS, out_cs);
    k_final<<<K_CODE, 128>>>(EA, out_cs, out_cb, out_ea, out_loss);
}

// round 17
// speedup vs baseline: 1.0652x; 1.0652x over previous
#include <cuda_runtime.h>
#include <cuda_bf16.h>
#include <cuda_fp16.h>
#include <cstdint>

// Problem constants
#define T_TOK 8192
#define K_CODE 8192
#define C_DIM 512
#define KSPLIT 512             // plain fp16 GEMM

// EMA / loss constants
#define DECAY_F 0.99f
#define OMD_F ((float)(1.0 - 0.99))
#define EPS_F 1e-5f
#define KEPS_F 0.08192f

#define MARGIN 0.125f          // ~20 sigma of fp16-accum dist error; worst case 3x covered
#define CAPG (1 << 22)         // global candidate list capacity (4M)

// -------- scratch (device globals; no allocation allowed) --------
__device__ __align__(16) unsigned long long g_keys[T_TOK];
__device__ __align__(16) unsigned g_amin[T_TOK];                        // f2ord(shifted min)
__device__ __align__(16) float g_stok[T_TOK];
__device__ __align__(16) float g_hcode[K_CODE];
__device__ __align__(16) float g_counts[K_CODE];
__device__ __align__(16) float g_embed_sum[(size_t)K_CODE * C_DIM];
__device__ __align__(16) __half g_A2h[(size_t)T_TOK * KSPLIT];          // fp16(Z)
__device__ __align__(16) __half g_B2h[(size_t)K_CODE * KSPLIT];         // fp16(E)
__device__ __align__(16) __half g_dh[(size_t)T_TOK * K_CODE];           // fp16 shifted dists
__device__ __align__(16) unsigned g_cand[CAPG];                         // (t<<13)|j
__device__ int g_ncand;
__device__ double g_loss;
__device__ float g_nsum;

// ------------------------------------------------------------------
// helpers
// ------------------------------------------------------------------
__device__ __forceinline__ uint32_t smem_u32(const void* p) {
    uint32_t a;
    asm("{ .reg .u64 t; cvta.to.shared.u64 t, %1; cvt.u32.u64 %0, t; }"
        : "=r"(a) : "l"(p));
    return a;
}
__device__ __forceinline__ unsigned f2ord(float f) {
    unsigned u = __float_as_uint(f);
    return (u & 0x80000000u) ? ~u : (u | 0x80000000u);
}
__device__ __forceinline__ float ord2f(unsigned u) {
    return (u & 0x80000000u) ? __uint_as_float(u & 0x7FFFFFFFu)
                             : __uint_as_float(~u);
}

#define LDSM_X4(r0, r1, r2, r3, addr) \
    asm volatile("ldmatrix.sync.aligned.m8n8.x4.shared.b16 {%0,%1,%2,%3}, [%4];" \
                 : "=r"(r0), "=r"(r1), "=r"(r2), "=r"(r3) : "r"(addr))

// ------------------------------------------------------------------
// K0: init scratch
// ------------------------------------------------------------------
__global__ void k_init() {
    size_t i = (size_t)blockIdx.x * blockDim.x + threadIdx.x;
    size_t stride = (size_t)gridDim.x * blockDim.x;
    float4 z4 = make_float4(0.f, 0.f, 0.f, 0.f);
    float4* es4 = (float4*)g_embed_sum;
    const size_t n4 = (size_t)K_CODE * C_DIM / 4;
    for (size_t j = i; j < n4; j += stride) es4[j] = z4;
    for (size_t j = i; j < K_CODE; j += stride) g_counts[j] = 0.f;
    for (size_t j = i; j < T_TOK; j += stride) { g_keys[j] = ~0ull; g_amin[j] = 0xFFFFFFFFu; }
    if (i == 0) { g_loss = 0.0; g_nsum = 0.f; g_ncand = 0; }
}

// ------------------------------------------------------------------
// K1: fused row norms + fp16 convert (one warp per row; rows 0..T-1 = Z,
//     rows T..T+K-1 = E). Norm computed EXACTLY like the R5 kernel.
// ------------------------------------------------------------------
__global__ void k_prep(const float* __restrict__ Z, const float* __restrict__ E) {
    int warp = (int)((blockIdx.x * blockDim.x + threadIdx.x) >> 5);
    int lane = threadIdx.x & 31;
    if (warp >= T_TOK + K_CODE) return;
    const bool isZ = warp < T_TOK;
    const int row = isZ ? warp : warp - T_TOK;
    const float* p = isZ ? (Z + (size_t)row * C_DIM) : (E + (size_t)row * C_DIM);
    __half* q = isZ ? (g_A2h + (size_t)row * KSPLIT) : (g_B2h + (size_t)row * KSPLIT);
    const float4* p4 = (const float4*)p;
    float s = 0.f;
#pragma unroll
    for (int i = 0; i < C_DIM / 128; i++) {
        float4 v = p4[lane + i * 32];
        s += v.x * v.x + v.y * v.y + v.z * v.z + v.w * v.w;
        __half2* q2 = (__half2*)(q + (lane + i * 32) * 4);
        q2[0] = __floats2half2_rn(v.x, v.y);
        q2[1] = __floats2half2_rn(v.z, v.w);
    }
#pragma unroll
    for (int off = 16; off; off >>= 1) s += __shfl_xor_sync(0xFFFFFFFFu, s, off);
    if (lane == 0) {
        if (isZ) g_stok[row] = s;
        else     g_hcode[row] = s;
    }
}

// ------------------------------------------------------------------
// K2: fp16 mma.sync GEMM (f16 accum) -> fp16 SHIFTED dists + f2ord minima.
//   CTA 128x128, 128 threads, 4 warps (2x2), warp tile 64x64.
//   fp16 accumulators halve acc regs (64/thread) -> 3 CTAs/SM = 12 warps.
//   NSTAGE=3 (61.4KB smem) so 3 CTAs fit in 227KB.
// ------------------------------------------------------------------
#define TILE_M 128
#define TILE_N 128
#define BKB 32
#define RST 40
#define STAGE_BF ((TILE_M + TILE_N) * RST)      // 10240 halves
#define STAGE_BYTES (STAGE_BF * 2)              // 20480
#define NSTAGE 3
#define SMEMB (NSTAGE * STAGE_BYTES)            // 61440
#define NIT (KSPLIT / BKB)                      // 16

__global__ __launch_bounds__(128, 3) void k_gemm_f16() {
    extern __shared__ __align__(16) __half smb[];
    const uint32_t sm_base = smem_u32(smb);
    const int tid = threadIdx.x;
    const int wid = tid >> 5, lane = tid & 31;
    const int g = lane >> 2, t = lane & 3;
    const int wm = wid >> 1, wn = wid & 1;     // 2 x 2 warp grid
    const int bm = blockIdx.y * TILE_M;
    const int bn = blockIdx.x * TILE_N;

    // fp16 accumulators: 2 u32 per mma (4 halves)
    uint32_t hacc[4][8][2];
#pragma unroll
    for (int a = 0; a < 4; a++)
#pragma unroll
        for (int b = 0; b < 8; b++) { hacc[a][b][0] = 0u; hacc[a][b][1] = 0u; }

    // cp.async mapping: 1024 16B-chunks per stage (256 rows x 4 segs), 8/thread
    const __half* srcp[8];
    uint32_t dsto[8];
#pragma unroll
    for (int i = 0; i < 8; i++) {
        int q = tid + i * 128;
        int row = q >> 2;
        int seg = q & 3;                 // 8 halves per 16B segment
        srcp[i] = (row < TILE_M)
                    ? (g_A2h + (size_t)(bm + row) * KSPLIT + seg * 8)
                    : (g_B2h + (size_t)(bn + (row - TILE_M)) * KSPLIT + seg * 8);
        dsto[i] = (uint32_t)(row * RST + seg * 8) * 2u;
    }

    auto load_stage = [&](int c) {
        uint32_t buf = (uint32_t)(c % NSTAGE) * STAGE_BYTES;
#pragma unroll
        for (int i = 0; i < 8; i++) {
            asm volatile("cp.async.cg.shared.global [%0], [%1], 16;"
                         :: "r"(sm_base + buf + dsto[i]),
                            "l"(srcp[i] + (size_t)c * BKB) : "memory");
        }
        asm volatile("cp.async.commit_group;" ::: "memory");
    };

    // ldmatrix per-lane element offsets (halves within a stage)
    const int lrow = lane & 7, blk = lane >> 3;
    const uint32_t a_elem = (uint32_t)((wm * 64 + (blk & 1) * 8 + lrow) * RST + (blk >> 1) * 8);
    uint32_t b_elem[4];
#pragma unroll
    for (int nfp = 0; nfp < 4; nfp++)
        b_elem[nfp] = (uint32_t)((TILE_M + wn * 64 + nfp * 16 + (blk >> 1) * 8 + lrow) * RST
                                 + (blk & 1) * 8);

    load_stage(0);
    load_stage(1);

    for (int c = 0; c < NIT; c++) {
        if (c + 1 < NIT) asm volatile("cp.async.wait_group 1;" ::: "memory");
        else             asm volatile("cp.async.wait_group 0;" ::: "memory");
        __syncthreads();                 // all warps past compute of stage c-1
        if (c + 2 < NIT) load_stage(c + 2);

        const uint32_t sbuf = sm_base + (uint32_t)(c % NSTAGE) * STAGE_BYTES;

#pragma unroll
        for (int ks = 0; ks < 2; ks++) {
            const uint32_t k0 = ks * 16;
            uint32_t af[4][4];
#pragma unroll
            for (int mf = 0; mf < 4; mf++) {
                uint32_t addr = sbuf + (a_elem + (uint32_t)(mf * 16 * RST) + k0) * 2u;
                LDSM_X4(af[mf][0], af[mf][1], af[mf][2], af[mf][3], addr);
            }
            uint32_t bfr[8][2];
#pragma unroll
            for (int nfp = 0; nfp < 4; nfp++) {
                uint32_t addr = sbuf + (b_elem[nfp] + k0) * 2u;
                LDSM_X4(bfr[2 * nfp][0], bfr[2 * nfp][1],
                        bfr[2 * nfp + 1][0], bfr[2 * nfp + 1][1], addr);
            }
#pragma unroll
            for (int mf = 0; mf < 4; mf++)
#pragma unroll
                for (int nf = 0; nf < 8; nf++) {
                    uint32_t* d = hacc[mf][nf];
                    asm volatile(
                        "mma.sync.aligned.m16n8k16.row.col.f16.f16.f16.f16 "
                        "{%0,%1}, {%2,%3,%4,%5}, {%6,%7}, {%0,%1};"
                        : "+r"(d[0]), "+r"(d[1])
                        : "r"(af[mf][0]), "r"(af[mf][1]), "r"(af[mf][2]), "r"(af[mf][3]),
                          "r"(bfr[nf][0]), "r"(bfr[nf][1]));
                }
        }
    }

    // ---- epilogue: store fp16 SHIFTED dists (h - 2*dot) + f2ord row minima ----
    // hacc reg0 = D[g][2t], D[g][2t+1]; reg1 = D[g+8][2t], D[g+8][2t+1]
#pragma unroll
    for (int mf = 0; mf < 4; mf++) {
        int r0 = bm + wm * 64 + mf * 16 + g;
        float m0 = 3.4e38f, m1 = 3.4e38f;
#pragma unroll
        for (int nf = 0; nf < 8; nf++) {
            int c0 = bn + wn * 64 + nf * 8 + 2 * t;
            float h0 = g_hcode[c0];
            float h1 = g_hcode[c0 + 1];
            float2 p0 = __half22float2(*(__half2*)&hacc[mf][nf][0]);
            float2 p1 = __half22float2(*(__half2*)&hacc[mf][nf][1]);
            float v00 = h0 - 2.0f * p0.x, v01 = h1 - 2.0f * p0.y;
            float v10 = h0 - 2.0f * p1.x, v11 = h1 - 2.0f * p1.y;
            *(__half2*)(g_dh + (size_t)r0 * K_CODE + c0) =
                __floats2half2_rn(v00, v01);
            *(__half2*)(g_dh + (size_t)(r0 + 8) * K_CODE + c0) =
                __floats2half2_rn(v10, v11);
            m0 = fminf(m0, fminf(v00, v01));
            m1 = fminf(m1, fminf(v10, v11));
        }
#pragma unroll
        for (int off = 1; off <= 2; off <<= 1) {
            m0 = fminf(m0, __shfl_xor_sync(0xFFFFFFFFu, m0, off));
            m1 = fminf(m1, __shfl_xor_sync(0xFFFFFFFFu, m1, off));
        }
        if (t == 0) {
            atomicMin(&g_amin[r0], f2ord(m0));
            atomicMin(&g_amin[r0 + 8], f2ord(m1));
        }
    }
}

// ------------------------------------------------------------------
// K2b: flat band scan. Grid-stride over the fp16 dist matrix, one uint4
//   (= 8 fp16, 16 bytes) per iteration; hits appended to a global list.
// ------------------------------------------------------------------
__global__ __launch_bounds__(256) void k_scan() {
    const size_t nchunk = (size_t)T_TOK * K_CODE / 8;
    size_t i = (size_t)blockIdx.x * blockDim.x + threadIdx.x;
    const size_t stride = (size_t)gridDim.x * blockDim.x;
    for (; i < nchunk; i += stride) {
        const int t = (int)(i >> 10);           // 1024 chunks per row (8192/8)
        const int col0 = (int)(i & 1023) << 3;
        const float thr = ord2f(g_amin[t]) + MARGIN;
        const uint4 v4 = *(const uint4*)(g_dh + (size_t)t * K_CODE + col0);
        const __half2* h2 = (const __half2*)&v4;   // 4 half2 = 8 values
#pragma unroll
        for (int q = 0; q < 4; q++) {
            float2 f = __half22float2(h2[q]);
            if (f.x < thr) {
                int p = atomicAdd(&g_ncand, 1);
                if (p < CAPG) g_cand[p] = ((unsigned)t << 13) | (unsigned)(col0 + 2 * q);
            }
            if (f.y < thr) {
                int p = atomicAdd(&g_ncand, 1);
                if (p < CAPG) g_cand[p] = ((unsigned)t << 13) | (unsigned)(col0 + 2 * q + 1);
            }
        }
    }
}

// ------------------------------------------------------------------
// K2c: exact re-check over the candidate list. ONE THREAD per candidate,
//   sequential ascending-k fmaf chain == the R5 oracle's operation order
//   -> g_keys bit-identical to the R5-passing kernel.
// ------------------------------------------------------------------
__global__ __launch_bounds__(256) void k_rlist(const float* __restrict__ Z,
                                               const float* __restrict__ E) {
    int n = g_ncand;
    if (n > CAPG) n = CAPG;
    int i = blockIdx.x * blockDim.x + threadIdx.x;
    const int stride = gridDim.x * blockDim.x;
    for (; i < n; i += stride) {
        const unsigned c = g_cand[i];
        const int t = (int)(c >> 13);
        const int j = (int)(c & 8191u);
        const float* zp = Z + (size_t)t * C_DIM;
        const float* ep = E + (size_t)j * C_DIM;
        float a = 0.f;
#pragma unroll 8
        for (int k = 0; k < C_DIM; k++) a = fmaf(zp[k], ep[k], a);  // sequential chain
        float dist = (g_stok[t] - 2.0f * a) + g_hcode[j];
        unsigned long long key = ((unsigned long long)f2ord(dist) << 32) | (unsigned)j;
        atomicMin(&g_keys[t], key);
    }
}

// ------------------------------------------------------------------
// K3: per-token: gather z_q, straight-through out, loss, counts,
//     embed_sum scatter. One block (128 threads) per token.
// ------------------------------------------------------------------
__global__ void k_token(const float* __restrict__ Z, const float* __restrict__ E,
                        float* __restrict__ out_zq, float* __restrict__ out_idx) {
    __shared__ float red[4];
    const int t = blockIdx.x;
    const int idx = (int)(g_keys[t] & 0xFFFFFFFFull);
    const float4* z4 = (const float4*)(Z + (size_t)t * C_DIM);
    const float4* e4 = (const float4*)(E + (size_t)idx * C_DIM);
    float4* o4 = (float4*)(out_zq + (size_t)t * C_DIM);
    float* es = g_embed_sum + (size_t)idx * C_DIM;

    const int i = threadIdx.x;
    float4 zv = z4[i];
    float4 ev = e4[i];
    float4 o;
    o.x = zv.x + (ev.x - zv.x);
    o.y = zv.y + (ev.y - zv.y);
    o.z = zv.z + (ev.z - zv.z);
    o.w = zv.w + (ev.w - zv.w);
    o4[i] = o;
    float dx = zv.x - ev.x, dy = zv.y - ev.y, dz = zv.z - ev.z, dw = zv.w - ev.w;
    float lsum = dx * dx + dy * dy + dz * dz + dw * dw;

    atomicAdd(&es[4 * i + 0], zv.x);
    atomicAdd(&es[4 * i + 1], zv.y);
    atomicAdd(&es[4 * i + 2], zv.z);
    atomicAdd(&es[4 * i + 3], zv.w);

#pragma unroll
    for (int off = 16; off; off >>= 1) lsum += __shfl_xor_sync(0xFFFFFFFFu, lsum, off);
    if ((i & 31) == 0) red[i >> 5] = lsum;
    __syncthreads();
    if (i == 0) {
        float tot = red[0] + red[1] + red[2] + red[3];
        out_idx[t] = (float)idx;
        atomicAdd(&g_counts[idx], 1.0f);
        atomicAdd(&g_loss, (double)tot);
    }
}

// ------------------------------------------------------------------
// K4: new_cluster_size + its global sum
// ------------------------------------------------------------------
__global__ void k_cluster(const float* __restrict__ cs, float* __restrict__ out_cs) {
    __shared__ float red[8];
    int k = blockIdx.x * 256 + threadIdx.x;
    float v = cs[k] * DECAY_F + g_counts[k] * OMD_F;
    out_cs[k] = v;
    float sum = v;
#pragma unroll
    for (int off = 16; off; off >>= 1) sum += __shfl_xor_sync(0xFFFFFFFFu, sum, off);
    if ((threadIdx.x & 31) == 0) red[threadIdx.x >> 5] = sum;
    __syncthreads();
    if (threadIdx.x == 0) {
        float tot = 0.f;
#pragma unroll
        for (int w = 0; w < 8; w++) tot += red[w];
        atomicAdd(&g_nsum, tot);
    }
}

// ------------------------------------------------------------------
// K5: new_embed_avg, new_codebook, vq_loss scalar.
// ------------------------------------------------------------------
__global__ void k_final(const float* __restrict__ ea, const float* __restrict__ ncs_arr,
                        float* __restrict__ out_cb, float* __restrict__ out_ea,
                        float* __restrict__ out_loss) {
    const int k = blockIdx.x;
    if (k == 0 && threadIdx.x == 0) {
        out_loss[0] = 0.25f * (float)(g_loss / (double)((size_t)T_TOK * C_DIM));
    }
    float n = fmaxf(g_nsum, 1.0f);
    float ncs = ncs_arr[k];
    float sm = (ncs + EPS_F) / (n + KEPS_F) * n;

    const float4* a4 = (const float4*)(ea + (size_t)k * C_DIM);
    const float4* s4 = (const float4*)(g_embed_sum + (size_t)k * C_DIM);
    const int i = threadIdx.x;
    float4 av = a4[i];
    float4 sv = s4[i];
    float ne[4];
    ne[0] = av.x * DECAY_F + sv.x * OMD_F;
    ne[1] = av.y * DECAY_F + sv.y * OMD_F;
    ne[2] = av.z * DECAY_F + sv.z * OMD_F;
    ne[3] = av.w * DECAY_F + sv.w * OMD_F;
    size_t base = (size_t)k * C_DIM + 4 * i;
#pragma unroll
    for (int j = 0; j < 4; j++) {
        out_ea[base + j] = ne[j];
        out_cb[base + j] = ne[j] / sm;   // out offsets are 1 mod 4 -> scalar stores
    }
}

// ------------------------------------------------------------------
// launch
// ------------------------------------------------------------------
extern "C" void kernel_launch(void* const* d_in, const int* in_sizes, int n_in,
                              void* d_out, int out_size) {
    const float* Z  = (const float*)d_in[0];
    const float* E  = (const float*)d_in[1];
    const float* CS = (const float*)d_in[2];
    const float* EA = (const float*)d_in[3];

    float* out = (float*)d_out;
    float* out_zq   = out;
    float* out_idx  = out_zq + (size_t)T_TOK * C_DIM;
    float* out_loss = out_idx + T_TOK;
    float* out_cb   = out_loss + 1;
    float* out_cs   = out_cb + (size_t)K_CODE * C_DIM;
    float* out_ea   = out_cs + K_CODE;

    cudaFuncSetAttribute(k_gemm_f16, cudaFuncAttributeMaxDynamicSharedMemorySize, SMEMB);

    k_init<<<2048, 256>>>();
    k_prep<<<(T_TOK + K_CODE) / 8, 256>>>(Z, E);
    dim3 grid(K_CODE / TILE_N, T_TOK / TILE_M);   // (64, 64)
    k_gemm_f16<<<grid, 128, SMEMB>>>();
    k_scan<<<2048, 256>>>();
    k_rlist<<<1024, 256>>>(Z, E);
    k_token<<<T_TOK, 128>>>(Z, E, out_zq, out_idx);
    k_cluster<<<K_CODE / 256, 256>>>(CS, out_cs);
    k_final<<<K_CODE, 128>>>(EA, out_cs, out_cb, out_ea, out_loss);
}